// round 5
// baseline (speedup 1.0000x reference)
#include <cuda_runtime.h>
#include <cuda_bf16.h>
#include <cstdint>

#define HIDDEN      512
#define NUM_LAYERS  8
#define BATCH       16384
#define NUM_OUTPUTS 16

// ---------------- device scratch (allocation-free rule) ----------------
__device__ __nv_bfloat16 g_whi[NUM_LAYERS * HIDDEN * HIDDEN];  // 4 MB
__device__ __nv_bfloat16 g_wlo[NUM_LAYERS * HIDDEN * HIDDEN];  // 4 MB
__device__ __nv_bfloat16 g_ahi[2][BATCH * HIDDEN];             // 2x16 MB
__device__ __nv_bfloat16 g_alo[2][BATCH * HIDDEN];             // 2x16 MB

// ---------------- helpers ----------------
__device__ __forceinline__ uint32_t smem_u32(const void* p) {
    return (uint32_t)__cvta_generic_to_shared(p);
}

#define CP_ASYNC16(dst, src) \
    asm volatile("cp.async.cg.shared.global [%0], [%1], 16;" :: "r"(dst), "l"(src))
#define CP_COMMIT() asm volatile("cp.async.commit_group;" ::: "memory")

#define LDSM_X4(r, addr)                                                        \
    asm volatile("ldmatrix.sync.aligned.m8n8.x4.shared.b16 {%0,%1,%2,%3}, [%4];"\
        : "=r"((r)[0]), "=r"((r)[1]), "=r"((r)[2]), "=r"((r)[3]) : "r"(addr))
#define LDSM_X2(r, addr)                                                        \
    asm volatile("ldmatrix.sync.aligned.m8n8.x2.shared.b16 {%0,%1}, [%2];"      \
        : "=r"((r)[0]), "=r"((r)[1]) : "r"(addr))

#define MMA16816(d, a, b)                                                       \
    asm volatile("mma.sync.aligned.m16n8k16.row.col.f32.bf16.bf16.f32 "         \
        "{%0,%1,%2,%3},{%4,%5,%6,%7},{%8,%9},{%0,%1,%2,%3};"                    \
        : "+f"((d)[0]), "+f"((d)[1]), "+f"((d)[2]), "+f"((d)[3])                \
        : "r"((a)[0]), "r"((a)[1]), "r"((a)[2]), "r"((a)[3]),                   \
          "r"((b)[0]), "r"((b)[1]))

__device__ __forceinline__ uint32_t pk2(float a, float b) {
    __nv_bfloat162 t = __floats2bfloat162_rn(a, b);
    return *reinterpret_cast<uint32_t*>(&t);
}
__device__ __forceinline__ void split_pack(float a, float b, uint32_t& hp, uint32_t& lp) {
    __nv_bfloat16 ha = __float2bfloat16_rn(a);
    __nv_bfloat16 hb = __float2bfloat16_rn(b);
    __nv_bfloat162 H = __halves2bfloat162(ha, hb);
    hp = *reinterpret_cast<uint32_t*>(&H);
    lp = pk2(a - __bfloat162float(ha), b - __bfloat162float(hb));
}

// XOR swizzle: 64B rows of 4x16B quads; q ^= (r>>1)&3 -> conflict-free ldmatrix
__device__ __forceinline__ uint32_t swz(int r, int q) {
    return (uint32_t)(r * 64 + ((q ^ ((r >> 1) & 3)) << 4));
}

// ---------------- weight prep: split W*wscale into bf16 hi/lo ----------------
__global__ void wprep_kernel(const float* __restrict__ w,
                             __nv_bfloat16* __restrict__ whi,
                             __nv_bfloat16* __restrict__ wlo) {
    size_t base = ((size_t)blockIdx.x * 256 + threadIdx.x) * 4;
    const float ws = 4.4194173824159216e-4f;  // 0.01 / sqrt(512)
    float4 v = *(const float4*)(w + base);
    uint2 H, L;
    split_pack(v.x * ws, v.y * ws, H.x, L.x);
    split_pack(v.z * ws, v.w * ws, H.y, L.y);
    *(uint2*)(whi + base) = H;
    *(uint2*)(wlo + base) = L;
}

// ---------------- pixel norm -> bf16 hi/lo ----------------
__global__ void pixnorm_kernel(const float* __restrict__ z,
                               __nv_bfloat16* __restrict__ ohi,
                               __nv_bfloat16* __restrict__ olo) {
    int row  = blockIdx.x * 8 + threadIdx.y;
    int lane = threadIdx.x;
    const float4* zr = (const float4*)(z + (size_t)row * HIDDEN);
    float4 v[4];
    float ss = 0.f;
#pragma unroll
    for (int i = 0; i < 4; i++) {
        v[i] = zr[lane + 32 * i];
        ss += v[i].x * v[i].x + v[i].y * v[i].y + v[i].z * v[i].z + v[i].w * v[i].w;
    }
#pragma unroll
    for (int o = 16; o > 0; o >>= 1) ss += __shfl_xor_sync(0xffffffff, ss, o);
    float s = rsqrtf(ss * (1.0f / 512.0f) + 1e-8f);
#pragma unroll
    for (int i = 0; i < 4; i++) {
        float4 t = v[i];
        t.x *= s; t.y *= s; t.z *= s; t.w *= s;
        uint2 H, L;
        split_pack(t.x, t.y, H.x, L.x);
        split_pack(t.z, t.w, H.y, L.y);
        size_t off = (size_t)row * HIDDEN + 4 * (lane + 32 * i);
        *(uint2*)(ohi + off) = H;
        *(uint2*)(olo + off) = L;
    }
}

// ---------------- HMMA GEMM + bias + lrelu (+ fused bcast on last) ----------
// CTA 128(M) x 256(N), 512 threads = 16 warps as 2(M) x 8(N), warp tile 64x32.
// 4 warps/SMSP for latency hiding. K chunks of 32, 4-stage cp.async pipeline.
// Stage: Ahi[128x64B]=8K | Alo=8K | Bhi[256x64B]=16K | Blo=16K = 48KB.
#define A_HI_OFF 0
#define A_LO_OFF 8192
#define B_HI_OFF 16384
#define B_LO_OFF 32768
#define STAGE_B  49152
#define NSTAGES  4
#define SMEM_BYTES (NSTAGES * STAGE_B)   // 196608

__global__ __launch_bounds__(512, 1) void gemm_mma_kernel(
    const __nv_bfloat16* __restrict__ Ahi, const __nv_bfloat16* __restrict__ Alo,
    const __nv_bfloat16* __restrict__ Whi, const __nv_bfloat16* __restrict__ Wlo,
    const float* __restrict__ bias,
    __nv_bfloat16* __restrict__ Ohi, __nv_bfloat16* __restrict__ Olo,
    float* __restrict__ outF, int last)
{
    extern __shared__ char smem[];
    const uint32_t sb = smem_u32(smem);
    const int tid  = threadIdx.x;
    const int lane = tid & 31;
    const int warp = tid >> 5;
    const int wm = warp >> 3;       // 0..1 (64-row tile)
    const int wn = warp & 7;        // 0..7 (32-col tile)
    const int m0 = blockIdx.y * 128;
    const int n0 = blockIdx.x * 256;

    float acc[4][4][4];
#pragma unroll
    for (int i = 0; i < 4; i++)
#pragma unroll
        for (int j = 0; j < 4; j++)
#pragma unroll
            for (int k = 0; k < 4; k++) acc[i][j][k] = 0.f;

    // ---- async loader: chunk c -> stage s. 3072 x 16B over 512 thr = 6 it ----
    auto load_chunk = [&](int c, int s) {
        const int k0 = c * 32;
        const uint32_t stb = sb + s * STAGE_B;
#pragma unroll
        for (int it = 0; it < 6; it++) {
            int o = it * 512 + tid;
            const __nv_bfloat16* src;
            uint32_t pbase;
            int idx;
            if (o < 512)       { src = Ahi; pbase = A_HI_OFF; idx = o; }
            else if (o < 1024) { src = Alo; pbase = A_LO_OFF; idx = o - 512; }
            else if (o < 2048) { src = Whi; pbase = B_HI_OFF; idx = o - 1024; }
            else               { src = Wlo; pbase = B_LO_OFF; idx = o - 2048; }
            int r = idx >> 2, q = idx & 3;
            int grow = (o < 1024) ? (m0 + r) : (n0 + r);
            CP_ASYNC16(stb + pbase + swz(r, q),
                       src + (size_t)grow * HIDDEN + k0 + q * 8);
        }
        CP_COMMIT();
    };

    load_chunk(0, 0);
    load_chunk(1, 1);
    load_chunk(2, 2);

    const int a_row = lane & 15;
    const int a_kh  = lane >> 4;
    const int b_row = lane & 7;
    const int b_kh  = (lane >> 3) & 1;

    for (int c = 0; c < 16; c++) {
        asm volatile("cp.async.wait_group 2;" ::: "memory");
        __syncthreads();
        if (c + 3 < 16) load_chunk(c + 3, (c + 3) & 3);

        const uint32_t st = sb + (c & 3) * STAGE_B;
#pragma unroll
        for (int ks = 0; ks < 2; ks++) {
            const int qa = ks * 2 + a_kh;
            const int qb = ks * 2 + b_kh;
            uint32_t bhi[4][2], blo_[4][2];
#pragma unroll
            for (int ni = 0; ni < 4; ni++) {
                int rB = wn * 32 + ni * 8 + b_row;
                uint32_t bd = st + B_HI_OFF + swz(rB, qb);
                LDSM_X2(bhi[ni], bd);
                LDSM_X2(blo_[ni], bd + (B_LO_OFF - B_HI_OFF));
            }
#pragma unroll
            for (int mi = 0; mi < 4; mi++) {
                int rA = wm * 64 + mi * 16 + a_row;
                uint32_t ad = st + A_HI_OFF + swz(rA, qa);
                uint32_t ahi[4], alo_[4];
                LDSM_X4(ahi, ad);
                LDSM_X4(alo_, ad + (A_LO_OFF - A_HI_OFF));
#pragma unroll
                for (int ni = 0; ni < 4; ni++) MMA16816(acc[mi][ni], ahi, bhi[ni]);
#pragma unroll
                for (int ni = 0; ni < 4; ni++) MMA16816(acc[mi][ni], ahi, blo_[ni]);
#pragma unroll
                for (int ni = 0; ni < 4; ni++) MMA16816(acc[mi][ni], alo_, bhi[ni]);
            }
        }
    }

    // ---- epilogue ----
    const float gain = 1.41421356237309515f;
    const int t4r = lane >> 2;
    const int t2c = (lane & 3) * 2;
#pragma unroll
    for (int ni = 0; ni < 4; ni++) {
        const int c0 = n0 + wn * 32 + ni * 8 + t2c;
        float2 b2 = *(const float2*)(bias + c0);
        const float bb0 = b2.x * 0.01f, bb1 = b2.y * 0.01f;
#pragma unroll
        for (int mi = 0; mi < 4; mi++) {
            const int r0 = m0 + wm * 64 + mi * 16 + t4r;
            float v0 = acc[mi][ni][0] + bb0;
            float v1 = acc[mi][ni][1] + bb1;
            float v2 = acc[mi][ni][2] + bb0;
            float v3 = acc[mi][ni][3] + bb1;
            v0 = (v0 > 0.f ? v0 : 0.2f * v0) * gain;
            v1 = (v1 > 0.f ? v1 : 0.2f * v1) * gain;
            v2 = (v2 > 0.f ? v2 : 0.2f * v2) * gain;
            v3 = (v3 > 0.f ? v3 : 0.2f * v3) * gain;
            if (!last) {
                uint32_t h01, l01, h23, l23;
                split_pack(v0, v1, h01, l01);
                split_pack(v2, v3, h23, l23);
                *(uint32_t*)(Ohi + (size_t)r0 * HIDDEN + c0)       = h01;
                *(uint32_t*)(Olo + (size_t)r0 * HIDDEN + c0)       = l01;
                *(uint32_t*)(Ohi + (size_t)(r0 + 8) * HIDDEN + c0) = h23;
                *(uint32_t*)(Olo + (size_t)(r0 + 8) * HIDDEN + c0) = l23;
            } else {
                float2 p01 = make_float2(v0, v1);
                float2 p23 = make_float2(v2, v3);
                float* o0 = outF + (size_t)r0 * NUM_OUTPUTS * HIDDEN + c0;
                float* o1 = outF + (size_t)(r0 + 8) * NUM_OUTPUTS * HIDDEN + c0;
#pragma unroll
                for (int j = 0; j < NUM_OUTPUTS; j++) {
                    *(float2*)(o0 + j * HIDDEN) = p01;
                    *(float2*)(o1 + j * HIDDEN) = p23;
                }
            }
        }
    }
}

// ---------------------------------------------------------------------------
extern "C" void kernel_launch(void* const* d_in, const int* in_sizes, int n_in,
                              void* d_out, int out_size) {
    const float* z    = (const float*)d_in[0];
    const float* w    = (const float*)d_in[1];
    const float* bias = (const float*)d_in[2];
    float* out = (float*)d_out;

    __nv_bfloat16 *whi, *wlo, *ahi, *alo;
    cudaGetSymbolAddress((void**)&whi, g_whi);
    cudaGetSymbolAddress((void**)&wlo, g_wlo);
    cudaGetSymbolAddress((void**)&ahi, g_ahi);
    cudaGetSymbolAddress((void**)&alo, g_alo);

    cudaFuncSetAttribute(gemm_mma_kernel,
                         cudaFuncAttributeMaxDynamicSharedMemorySize, SMEM_BYTES);

    // 1) weight split
    wprep_kernel<<<2048, 256>>>(w, whi, wlo);
    // 2) pixel norm + split
    pixnorm_kernel<<<BATCH / 8, dim3(32, 8)>>>(z, ahi, alo);
    // 3) 8 HMMA layers, ping-pong; last fuses broadcast into epilogue
    for (int l = 0; l < NUM_LAYERS; l++) {
        int pi = l & 1, po = pi ^ 1;
        gemm_mma_kernel<<<dim3(HIDDEN / 256, BATCH / 128), 512, SMEM_BYTES>>>(
            ahi + (size_t)pi * BATCH * HIDDEN, alo + (size_t)pi * BATCH * HIDDEN,
            whi + (size_t)l * HIDDEN * HIDDEN, wlo + (size_t)l * HIDDEN * HIDDEN,
            bias + l * HIDDEN,
            ahi + (size_t)po * BATCH * HIDDEN, alo + (size_t)po * BATCH * HIDDEN,
            out, (l == NUM_LAYERS - 1) ? 1 : 0);
    }
}

// round 8
// speedup vs baseline: 1.8428x; 1.8428x over previous
#include <cuda_runtime.h>
#include <cuda_bf16.h>
#include <cstdint>

#define HIDDEN      512
#define NUM_LAYERS  8
#define BATCH       16384
#define NUM_OUTPUTS 16

// ---------------- device scratch (allocation-free rule) ----------------
__device__ __nv_bfloat16 g_whi[NUM_LAYERS * HIDDEN * HIDDEN];  // 4 MB
__device__ __nv_bfloat16 g_ahi[2][BATCH * HIDDEN];             // 2x16 MB

// ---------------- helpers ----------------
__device__ __forceinline__ uint32_t smem_u32(const void* p) {
    return (uint32_t)__cvta_generic_to_shared(p);
}

#define CP_ASYNC16(dst, src) \
    asm volatile("cp.async.cg.shared.global [%0], [%1], 16;" :: "r"(dst), "l"(src))
#define CP_COMMIT() asm volatile("cp.async.commit_group;" ::: "memory")

#define LDSM_X4(r, addr)                                                        \
    asm volatile("ldmatrix.sync.aligned.m8n8.x4.shared.b16 {%0,%1,%2,%3}, [%4];"\
        : "=r"((r)[0]), "=r"((r)[1]), "=r"((r)[2]), "=r"((r)[3]) : "r"(addr))
#define LDSM_X2(r, addr)                                                        \
    asm volatile("ldmatrix.sync.aligned.m8n8.x2.shared.b16 {%0,%1}, [%2];"      \
        : "=r"((r)[0]), "=r"((r)[1]) : "r"(addr))

#define MMA16816(d, a, b)                                                       \
    asm volatile("mma.sync.aligned.m16n8k16.row.col.f32.bf16.bf16.f32 "         \
        "{%0,%1,%2,%3},{%4,%5,%6,%7},{%8,%9},{%0,%1,%2,%3};"                    \
        : "+f"((d)[0]), "+f"((d)[1]), "+f"((d)[2]), "+f"((d)[3])                \
        : "r"((a)[0]), "r"((a)[1]), "r"((a)[2]), "r"((a)[3]),                   \
          "r"((b)[0]), "r"((b)[1]))

__device__ __forceinline__ uint32_t pk2(float a, float b) {
    __nv_bfloat162 t = __floats2bfloat162_rn(a, b);
    return *reinterpret_cast<uint32_t*>(&t);
}

// XOR swizzle: 64B rows of 4x16B quads; q ^= (r>>1)&3 -> conflict-free ldmatrix
__device__ __forceinline__ uint32_t swz(int r, int q) {
    return (uint32_t)(r * 64 + ((q ^ ((r >> 1) & 3)) << 4));
}

// ---------------- weight prep: W*wscale -> bf16 ----------------
__global__ void wprep_kernel(const float* __restrict__ w,
                             __nv_bfloat16* __restrict__ whi) {
    size_t base = ((size_t)blockIdx.x * 256 + threadIdx.x) * 4;
    const float ws = 4.4194173824159216e-4f;  // 0.01 / sqrt(512)
    float4 v = *(const float4*)(w + base);
    uint2 H;
    H.x = pk2(v.x * ws, v.y * ws);
    H.y = pk2(v.z * ws, v.w * ws);
    *(uint2*)(whi + base) = H;
}

// ---------------- pixel norm -> bf16 ----------------
__global__ void pixnorm_kernel(const float* __restrict__ z,
                               __nv_bfloat16* __restrict__ ohi) {
    int row  = blockIdx.x * 8 + threadIdx.y;
    int lane = threadIdx.x;
    const float4* zr = (const float4*)(z + (size_t)row * HIDDEN);
    float4 v[4];
    float ss = 0.f;
#pragma unroll
    for (int i = 0; i < 4; i++) {
        v[i] = zr[lane + 32 * i];
        ss += v[i].x * v[i].x + v[i].y * v[i].y + v[i].z * v[i].z + v[i].w * v[i].w;
    }
#pragma unroll
    for (int o = 16; o > 0; o >>= 1) ss += __shfl_xor_sync(0xffffffff, ss, o);
    float s = rsqrtf(ss * (1.0f / 512.0f) + 1e-8f);
#pragma unroll
    for (int i = 0; i < 4; i++) {
        float4 t = v[i];
        uint2 H;
        H.x = pk2(t.x * s, t.y * s);
        H.y = pk2(t.z * s, t.w * s);
        *(uint2*)(ohi + (size_t)row * HIDDEN + 4 * (lane + 32 * i)) = H;
    }
}

// ---------------- bf16 HMMA GEMM + bias + lrelu (+ fused bcast last) -------
// CTA 128(M) x 256(N), 512 threads = 16 warps as 2(M) x 8(N), warp tile 64x32.
// K chunks of 32, 4-stage cp.async pipeline, XOR-swizzled 64B smem rows.
// Stage: A[128x64B]=8K | B[256x64B]=16K = 24KB.
#define A_OFF    0
#define B_OFF    8192
#define STAGE_B  24576
#define NSTAGES  4
#define SMEM_BYTES (NSTAGES * STAGE_B)   // 98304

__global__ __launch_bounds__(512, 1) void gemm_mma_kernel(
    const __nv_bfloat16* __restrict__ Ahi,
    const __nv_bfloat16* __restrict__ Whi,
    const float* __restrict__ bias,
    __nv_bfloat16* __restrict__ Ohi,
    float* __restrict__ outF, int last)
{
    extern __shared__ char smem[];
    const uint32_t sb = smem_u32(smem);
    const int tid  = threadIdx.x;
    const int lane = tid & 31;
    const int warp = tid >> 5;
    const int wm = warp >> 3;       // 0..1 (64-row tile)
    const int wn = warp & 7;        // 0..7 (32-col tile)
    const int m0 = blockIdx.y * 128;
    const int n0 = blockIdx.x * 256;

    float acc[4][4][4];
#pragma unroll
    for (int i = 0; i < 4; i++)
#pragma unroll
        for (int j = 0; j < 4; j++)
#pragma unroll
            for (int k = 0; k < 4; k++) acc[i][j][k] = 0.f;

    // ---- async loader: chunk c -> stage s. 1536 x 16B over 512 thr = 3 it ----
    auto load_chunk = [&](int c, int s) {
        const int k0 = c * 32;
        const uint32_t stb = sb + s * STAGE_B;
#pragma unroll
        for (int it = 0; it < 3; it++) {
            int o = it * 512 + tid;
            const __nv_bfloat16* src;
            uint32_t pbase;
            int idx, grow;
            if (o < 512) { src = Ahi; pbase = A_OFF; idx = o;       grow = m0 + (idx >> 2); }
            else         { src = Whi; pbase = B_OFF; idx = o - 512; grow = n0 + (idx >> 2); }
            int r = idx >> 2, q = idx & 3;
            CP_ASYNC16(stb + pbase + swz(r, q),
                       src + (size_t)grow * HIDDEN + k0 + q * 8);
        }
        CP_COMMIT();
    };

    load_chunk(0, 0);
    load_chunk(1, 1);
    load_chunk(2, 2);

    const int a_row = lane & 15;
    const int a_kh  = lane >> 4;
    const int b_row = lane & 7;
    const int b_kh  = (lane >> 3) & 1;

    for (int c = 0; c < 16; c++) {
        asm volatile("cp.async.wait_group 2;" ::: "memory");
        __syncthreads();
        if (c + 3 < 16) load_chunk(c + 3, (c + 3) & 3);

        const uint32_t st = sb + (c & 3) * STAGE_B;
#pragma unroll
        for (int ks = 0; ks < 2; ks++) {
            const int qa = ks * 2 + a_kh;
            const int qb = ks * 2 + b_kh;
            uint32_t bf[4][2];
#pragma unroll
            for (int ni = 0; ni < 4; ni++) {
                int rB = wn * 32 + ni * 8 + b_row;
                LDSM_X2(bf[ni], st + B_OFF + swz(rB, qb));
            }
#pragma unroll
            for (int mi = 0; mi < 4; mi++) {
                int rA = wm * 64 + mi * 16 + a_row;
                uint32_t af[4];
                LDSM_X4(af, st + A_OFF + swz(rA, qa));
#pragma unroll
                for (int ni = 0; ni < 4; ni++) MMA16816(acc[mi][ni], af, bf[ni]);
            }
        }
    }

    // ---- epilogue ----
    const float gain = 1.41421356237309515f;
    const int t4r = lane >> 2;
    const int t2c = (lane & 3) * 2;
#pragma unroll
    for (int ni = 0; ni < 4; ni++) {
        const int c0 = n0 + wn * 32 + ni * 8 + t2c;
        float2 b2 = *(const float2*)(bias + c0);
        const float bb0 = b2.x * 0.01f, bb1 = b2.y * 0.01f;
#pragma unroll
        for (int mi = 0; mi < 4; mi++) {
            const int r0 = m0 + wm * 64 + mi * 16 + t4r;
            float v0 = acc[mi][ni][0] + bb0;
            float v1 = acc[mi][ni][1] + bb1;
            float v2 = acc[mi][ni][2] + bb0;
            float v3 = acc[mi][ni][3] + bb1;
            v0 = (v0 > 0.f ? v0 : 0.2f * v0) * gain;
            v1 = (v1 > 0.f ? v1 : 0.2f * v1) * gain;
            v2 = (v2 > 0.f ? v2 : 0.2f * v2) * gain;
            v3 = (v3 > 0.f ? v3 : 0.2f * v3) * gain;
            if (!last) {
                *(uint32_t*)(Ohi + (size_t)r0 * HIDDEN + c0)       = pk2(v0, v1);
                *(uint32_t*)(Ohi + (size_t)(r0 + 8) * HIDDEN + c0) = pk2(v2, v3);
            } else {
                float2 p01 = make_float2(v0, v1);
                float2 p23 = make_float2(v2, v3);
                float* o0 = outF + (size_t)r0 * NUM_OUTPUTS * HIDDEN + c0;
                float* o1 = outF + (size_t)(r0 + 8) * NUM_OUTPUTS * HIDDEN + c0;
#pragma unroll
                for (int j = 0; j < NUM_OUTPUTS; j++) {
                    *(float2*)(o0 + j * HIDDEN) = p01;
                    *(float2*)(o1 + j * HIDDEN) = p23;
                }
            }
        }
    }
}

// ---------------------------------------------------------------------------
extern "C" void kernel_launch(void* const* d_in, const int* in_sizes, int n_in,
                              void* d_out, int out_size) {
    const float* z    = (const float*)d_in[0];
    const float* w    = (const float*)d_in[1];
    const float* bias = (const float*)d_in[2];
    float* out = (float*)d_out;

    __nv_bfloat16 *whi, *ahi;
    cudaGetSymbolAddress((void**)&whi, g_whi);
    cudaGetSymbolAddress((void**)&ahi, g_ahi);

    cudaFuncSetAttribute(gemm_mma_kernel,
                         cudaFuncAttributeMaxDynamicSharedMemorySize, SMEM_BYTES);

    // 1) weight scale -> bf16
    wprep_kernel<<<2048, 256>>>(w, whi);
    // 2) pixel norm -> bf16
    pixnorm_kernel<<<BATCH / 8, dim3(32, 8)>>>(z, ahi);
    // 3) 8 bf16 HMMA layers, ping-pong; last fuses broadcast into epilogue
    for (int l = 0; l < NUM_LAYERS; l++) {
        int pi = l & 1, po = pi ^ 1;
        gemm_mma_kernel<<<dim3(HIDDEN / 256, BATCH / 128), 512, SMEM_BYTES>>>(
            ahi + (size_t)pi * BATCH * HIDDEN,
            whi + (size_t)l * HIDDEN * HIDDEN,
            bias + l * HIDDEN,
            ahi + (size_t)po * BATCH * HIDDEN,
            out, (l == NUM_LAYERS - 1) ? 1 : 0);
    }
}

// round 9
// speedup vs baseline: 1.8664x; 1.0128x over previous
#include <cuda_runtime.h>
#include <cuda_bf16.h>
#include <cstdint>

#define HIDDEN      512
#define NUM_LAYERS  8
#define BATCH       16384
#define NUM_OUTPUTS 16

// ---------------- device scratch (allocation-free rule) ----------------
__device__ __nv_bfloat16 g_whi[NUM_LAYERS * HIDDEN * HIDDEN];  // 4 MB
__device__ __nv_bfloat16 g_ahi[2][BATCH * HIDDEN];             // 2x16 MB

// ---------------- helpers ----------------
__device__ __forceinline__ uint32_t smem_u32(const void* p) {
    return (uint32_t)__cvta_generic_to_shared(p);
}

#define CP_ASYNC16(dst, src) \
    asm volatile("cp.async.cg.shared.global [%0], [%1], 16;" :: "r"(dst), "l"(src))
#define CP_COMMIT() asm volatile("cp.async.commit_group;" ::: "memory")

#define LDSM_X4(r, addr)                                                        \
    asm volatile("ldmatrix.sync.aligned.m8n8.x4.shared.b16 {%0,%1,%2,%3}, [%4];"\
        : "=r"((r)[0]), "=r"((r)[1]), "=r"((r)[2]), "=r"((r)[3]) : "r"(addr))

#define MMA16816(d, a, b)                                                       \
    asm volatile("mma.sync.aligned.m16n8k16.row.col.f32.bf16.bf16.f32 "         \
        "{%0,%1,%2,%3},{%4,%5,%6,%7},{%8,%9},{%0,%1,%2,%3};"                    \
        : "+f"((d)[0]), "+f"((d)[1]), "+f"((d)[2]), "+f"((d)[3])                \
        : "r"((a)[0]), "r"((a)[1]), "r"((a)[2]), "r"((a)[3]),                   \
          "r"((b)[0]), "r"((b)[1]))

__device__ __forceinline__ uint32_t pk2(float a, float b) {
    __nv_bfloat162 t = __floats2bfloat162_rn(a, b);
    return *reinterpret_cast<uint32_t*>(&t);
}

// SW128 swizzle for 128B rows: quad q (16B) of row r -> q ^= (r & 7)
__device__ __forceinline__ uint32_t swz128(int r, int q) {
    return (uint32_t)(r * 128 + ((q ^ (r & 7)) << 4));
}

// ---------------- weight prep: W*wscale -> bf16 ----------------
__global__ void wprep_kernel(const float* __restrict__ w,
                             __nv_bfloat16* __restrict__ whi) {
    size_t base = ((size_t)blockIdx.x * 256 + threadIdx.x) * 4;
    const float ws = 4.4194173824159216e-4f;  // 0.01 / sqrt(512)
    float4 v = *(const float4*)(w + base);
    uint2 H;
    H.x = pk2(v.x * ws, v.y * ws);
    H.y = pk2(v.z * ws, v.w * ws);
    *(uint2*)(whi + base) = H;
}

// ---------------- pixel norm -> bf16 ----------------
__global__ void pixnorm_kernel(const float* __restrict__ z,
                               __nv_bfloat16* __restrict__ ohi) {
    int row  = blockIdx.x * 8 + threadIdx.y;
    int lane = threadIdx.x;
    const float4* zr = (const float4*)(z + (size_t)row * HIDDEN);
    float4 v[4];
    float ss = 0.f;
#pragma unroll
    for (int i = 0; i < 4; i++) {
        v[i] = zr[lane + 32 * i];
        ss += v[i].x * v[i].x + v[i].y * v[i].y + v[i].z * v[i].z + v[i].w * v[i].w;
    }
#pragma unroll
    for (int o = 16; o > 0; o >>= 1) ss += __shfl_xor_sync(0xffffffff, ss, o);
    float s = rsqrtf(ss * (1.0f / 512.0f) + 1e-8f);
#pragma unroll
    for (int i = 0; i < 4; i++) {
        float4 t = v[i];
        uint2 H;
        H.x = pk2(t.x * s, t.y * s);
        H.y = pk2(t.z * s, t.w * s);
        *(uint2*)(ohi + (size_t)row * HIDDEN + 4 * (lane + 32 * i)) = H;
    }
}

// ---------------- bf16 HMMA GEMM + bias + lrelu (+ fused bcast last) -------
// CTA 128(M) x 256(N), 256 threads = 8 warps as 2(M) x 4(N), warp tile 64x64.
// K chunks of 64 (128B smem rows, SW128 swizzle), 3-stage cp.async pipeline.
// Stage: A[128x128B]=16K | B[256x128B]=32K = 48KB. 3 stages = 144KB.
#define A_OFF    0
#define B_OFF    16384
#define STAGE_B  49152
#define NSTAGES  3
#define SMEM_BYTES (NSTAGES * STAGE_B)   // 147456
#define NCHUNK   8

__global__ __launch_bounds__(256, 1) void gemm_mma_kernel(
    const __nv_bfloat16* __restrict__ Ahi,
    const __nv_bfloat16* __restrict__ Whi,
    const float* __restrict__ bias,
    __nv_bfloat16* __restrict__ Ohi,
    float* __restrict__ outF, int last)
{
    extern __shared__ char smem[];
    const uint32_t sb = smem_u32(smem);
    const int tid  = threadIdx.x;
    const int lane = tid & 31;
    const int warp = tid >> 5;
    const int wm = warp >> 2;       // 0..1 (64-row tile)
    const int wn = warp & 3;        // 0..3 (64-col tile)
    const int m0 = blockIdx.y * 128;
    const int n0 = blockIdx.x * 256;

    float acc[4][8][4];
#pragma unroll
    for (int i = 0; i < 4; i++)
#pragma unroll
        for (int j = 0; j < 8; j++)
#pragma unroll
            for (int k = 0; k < 4; k++) acc[i][j][k] = 0.f;

    // ---- async loader: chunk c (64 k) -> stage s. 3072 x 16B / 256 thr = 12 it
    auto load_chunk = [&](int c, int s) {
        const int k0 = c * 64;
        const uint32_t stb = sb + s * STAGE_B;
#pragma unroll
        for (int it = 0; it < 12; it++) {
            int o = it * 256 + tid;
            const __nv_bfloat16* src;
            uint32_t pbase;
            int idx, grow;
            if (o < 1024) { src = Ahi; pbase = A_OFF; idx = o;        grow = m0 + (idx >> 3); }
            else          { src = Whi; pbase = B_OFF; idx = o - 1024; grow = n0 + (idx >> 3); }
            int r = idx >> 3, q = idx & 7;
            CP_ASYNC16(stb + pbase + swz128(r, q),
                       src + (size_t)grow * HIDDEN + k0 + q * 8);
        }
        CP_COMMIT();
    };

    load_chunk(0, 0);
    load_chunk(1, 1);

    // ldmatrix lane addressing
    const int a_row = lane & 15;          // row within m16
    const int a_kh  = lane >> 4;          // k-half quad
    const int b_rlo = lane & 7;           // row within n8
    const int b_kh  = (lane >> 3) & 1;    // k-half quad
    const int b_nn  = lane >> 4;          // which n8 of the pair

    for (int c = 0; c < NCHUNK; c++) {
        if (c < NCHUNK - 1) asm volatile("cp.async.wait_group 1;" ::: "memory");
        else                asm volatile("cp.async.wait_group 0;" ::: "memory");
        __syncthreads();
        if (c + 2 < NCHUNK) load_chunk(c + 2, (c + 2) % NSTAGES);

        const uint32_t st = sb + (c % NSTAGES) * STAGE_B;
#pragma unroll
        for (int ks = 0; ks < 4; ks++) {
            // B fragments: 8 n8-blocks via 4 LDSM_X4 (two blocks each)
            uint32_t bf[4][4];
#pragma unroll
            for (int nj = 0; nj < 4; nj++) {
                int rB = wn * 64 + nj * 16 + b_nn * 8 + b_rlo;
                LDSM_X4(bf[nj], st + B_OFF + swz128(rB, ks * 2 + b_kh));
            }
#pragma unroll
            for (int mi = 0; mi < 4; mi++) {
                int rA = wm * 64 + mi * 16 + a_row;
                uint32_t af[4];
                LDSM_X4(af, st + A_OFF + swz128(rA, ks * 2 + a_kh));
#pragma unroll
                for (int nj = 0; nj < 4; nj++) {
                    MMA16816(acc[mi][nj * 2 + 0], af, (&bf[nj][0]));
                    MMA16816(acc[mi][nj * 2 + 1], af, (&bf[nj][2]));
                }
            }
        }
    }

    // ---- epilogue ----
    const float gain = 1.41421356237309515f;
    const int t4r = lane >> 2;
    const int t2c = (lane & 3) * 2;
#pragma unroll
    for (int ni = 0; ni < 8; ni++) {
        const int c0 = n0 + wn * 64 + ni * 8 + t2c;
        float2 b2 = *(const float2*)(bias + c0);
        const float bb0 = b2.x * 0.01f, bb1 = b2.y * 0.01f;
#pragma unroll
        for (int mi = 0; mi < 4; mi++) {
            const int r0 = m0 + wm * 64 + mi * 16 + t4r;
            float v0 = acc[mi][ni][0] + bb0;
            float v1 = acc[mi][ni][1] + bb1;
            float v2 = acc[mi][ni][2] + bb0;
            float v3 = acc[mi][ni][3] + bb1;
            v0 = (v0 > 0.f ? v0 : 0.2f * v0) * gain;
            v1 = (v1 > 0.f ? v1 : 0.2f * v1) * gain;
            v2 = (v2 > 0.f ? v2 : 0.2f * v2) * gain;
            v3 = (v3 > 0.f ? v3 : 0.2f * v3) * gain;
            if (!last) {
                *(uint32_t*)(Ohi + (size_t)r0 * HIDDEN + c0)       = pk2(v0, v1);
                *(uint32_t*)(Ohi + (size_t)(r0 + 8) * HIDDEN + c0) = pk2(v2, v3);
            } else {
                float2 p01 = make_float2(v0, v1);
                float2 p23 = make_float2(v2, v3);
                float* o0 = outF + (size_t)r0 * NUM_OUTPUTS * HIDDEN + c0;
                float* o1 = outF + (size_t)(r0 + 8) * NUM_OUTPUTS * HIDDEN + c0;
#pragma unroll
                for (int j = 0; j < NUM_OUTPUTS; j++) {
                    *(float2*)(o0 + j * HIDDEN) = p01;
                    *(float2*)(o1 + j * HIDDEN) = p23;
                }
            }
        }
    }
}

// ---------------------------------------------------------------------------
extern "C" void kernel_launch(void* const* d_in, const int* in_sizes, int n_in,
                              void* d_out, int out_size) {
    const float* z    = (const float*)d_in[0];
    const float* w    = (const float*)d_in[1];
    const float* bias = (const float*)d_in[2];
    float* out = (float*)d_out;

    __nv_bfloat16 *whi, *ahi;
    cudaGetSymbolAddress((void**)&whi, g_whi);
    cudaGetSymbolAddress((void**)&ahi, g_ahi);

    cudaFuncSetAttribute(gemm_mma_kernel,
                         cudaFuncAttributeMaxDynamicSharedMemorySize, SMEM_BYTES);

    // 1) weight scale -> bf16
    wprep_kernel<<<2048, 256>>>(w, whi);
    // 2) pixel norm -> bf16
    pixnorm_kernel<<<BATCH / 8, dim3(32, 8)>>>(z, ahi);
    // 3) 8 bf16 HMMA layers, ping-pong; last fuses broadcast into epilogue
    for (int l = 0; l < NUM_LAYERS; l++) {
        int pi = l & 1, po = pi ^ 1;
        gemm_mma_kernel<<<dim3(HIDDEN / 256, BATCH / 128), 256, SMEM_BYTES>>>(
            ahi + (size_t)pi * BATCH * HIDDEN,
            whi + (size_t)l * HIDDEN * HIDDEN,
            bias + l * HIDDEN,
            ahi + (size_t)po * BATCH * HIDDEN,
            out, (l == NUM_LAYERS - 1) ? 1 : 0);
    }
}

// round 10
// speedup vs baseline: 2.6037x; 1.3950x over previous
#include <cuda_runtime.h>
#include <cuda_bf16.h>
#include <cstdint>

#define HIDDEN      512
#define NUM_LAYERS  8
#define BATCH       16384
#define NUM_OUTPUTS 16

// ---------------- device scratch (allocation-free rule) ----------------
__device__ __nv_bfloat16 g_whi[NUM_LAYERS * HIDDEN * HIDDEN];  // 4 MB
__device__ __nv_bfloat16 g_ahi[BATCH * HIDDEN];                // 16 MB

// ---------------- helpers ----------------
__device__ __forceinline__ uint32_t smem_u32(const void* p) {
    return (uint32_t)__cvta_generic_to_shared(p);
}

#define CP_ASYNC16(dst, src) \
    asm volatile("cp.async.cg.shared.global [%0], [%1], 16;" :: "r"(dst), "l"(src))
#define CP_COMMIT() asm volatile("cp.async.commit_group;" ::: "memory")

#define LDSM_X4(r, addr)                                                        \
    asm volatile("ldmatrix.sync.aligned.m8n8.x4.shared.b16 {%0,%1,%2,%3}, [%4];"\
        : "=r"((r)[0]), "=r"((r)[1]), "=r"((r)[2]), "=r"((r)[3]) : "r"(addr))

#define MMA16816(d, a, b)                                                       \
    asm volatile("mma.sync.aligned.m16n8k16.row.col.f32.bf16.bf16.f32 "         \
        "{%0,%1,%2,%3},{%4,%5,%6,%7},{%8,%9},{%0,%1,%2,%3};"                    \
        : "+f"((d)[0]), "+f"((d)[1]), "+f"((d)[2]), "+f"((d)[3])                \
        : "r"((a)[0]), "r"((a)[1]), "r"((a)[2]), "r"((a)[3]),                   \
          "r"((b)[0]), "r"((b)[1]))

__device__ __forceinline__ uint32_t pk2(float a, float b) {
    __nv_bfloat162 t = __floats2bfloat162_rn(a, b);
    return *reinterpret_cast<uint32_t*>(&t);
}

// B-stage swizzle: 64B rows of 4x16B quads; q ^= (r>>1)&3
__device__ __forceinline__ uint32_t swzB(int r, int q) {
    return (uint32_t)(r * 64 + ((q ^ ((r >> 1) & 3)) << 4));
}
// X swizzle: 1024B rows; within each 128B block, quad q ^= (r&7)
__device__ __forceinline__ uint32_t xbyte(int r, int cbyte) {
    int blk = cbyte >> 7;
    int q   = (cbyte >> 4) & 7;
    int o   = cbyte & 15;
    return (uint32_t)(r * 1024 + blk * 128 + ((q ^ (r & 7)) << 4) + o);
}

// ---------------- weight prep: W*wscale -> bf16 ----------------
__global__ void wprep_kernel(const float* __restrict__ w,
                             __nv_bfloat16* __restrict__ whi) {
    size_t base = ((size_t)blockIdx.x * 256 + threadIdx.x) * 4;
    const float ws = 4.4194173824159216e-4f;  // 0.01 / sqrt(512)
    float4 v = *(const float4*)(w + base);
    uint2 H;
    H.x = pk2(v.x * ws, v.y * ws);
    H.y = pk2(v.z * ws, v.w * ws);
    *(uint2*)(whi + base) = H;
}

// ---------------- pixel norm -> bf16 ----------------
__global__ void pixnorm_kernel(const float* __restrict__ z,
                               __nv_bfloat16* __restrict__ ohi) {
    int row  = blockIdx.x * 8 + threadIdx.y;
    int lane = threadIdx.x;
    const float4* zr = (const float4*)(z + (size_t)row * HIDDEN);
    float4 v[4];
    float ss = 0.f;
#pragma unroll
    for (int i = 0; i < 4; i++) {
        v[i] = zr[lane + 32 * i];
        ss += v[i].x * v[i].x + v[i].y * v[i].y + v[i].z * v[i].z + v[i].w * v[i].w;
    }
#pragma unroll
    for (int o = 16; o > 0; o >>= 1) ss += __shfl_xor_sync(0xffffffff, ss, o);
    float s = rsqrtf(ss * (1.0f / 512.0f) + 1e-8f);
#pragma unroll
    for (int i = 0; i < 4; i++) {
        float4 t = v[i];
        uint2 H;
        H.x = pk2(t.x * s, t.y * s);
        H.y = pk2(t.z * s, t.w * s);
        *(uint2*)(ohi + (size_t)row * HIDDEN + 4 * (lane + 32 * i)) = H;
    }
}

// ---------------- fused 8-layer mapping network ----------------------------
// One CTA owns 64 batch rows through ALL 8 layers. x resident in smem (bf16,
// rewritten in place per layer). W streams via 3-stage cp.async (32-k chunks,
// 16 chunks/layer, 128 chunks total, continuous across layers).
// 256 threads = 8 warps, warp tile 64(M) x 64(N) (wn = warp, all warps share A).
// SMEM: X[64x1024B]=64K @0 | Bstage 3x32K @65536. Final fp32 staging reuses @0.
#define X_OFF    0
#define BST_OFF  65536
#define BSTAGE_B 32768
#define SMEM_BYTES (BST_OFF + 3 * BSTAGE_B)   // 163840

__global__ __launch_bounds__(256, 1) void fused_mlp_kernel(
    const __nv_bfloat16* __restrict__ Ahi,
    const __nv_bfloat16* __restrict__ Whi,
    const float* __restrict__ bias,
    float* __restrict__ outF)
{
    extern __shared__ char smem[];
    const uint32_t sb = smem_u32(smem);
    const int tid  = threadIdx.x;
    const int lane = tid & 31;
    const int wn   = tid >> 5;            // 0..7: 64-col slice
    const int m0   = blockIdx.x * 64;

    // ---- initial X load: 64 rows x 1024B, swizzled ----
#pragma unroll
    for (int it = 0; it < 16; it++) {
        int o = it * 256 + tid;           // 0..4095 (16B quads)
        int r = o >> 6, kq = o & 63;
        CP_ASYNC16(sb + X_OFF + xbyte(r, kq * 16),
                   Ahi + (size_t)(m0 + r) * HIDDEN + kq * 8);
    }
    CP_COMMIT();

    // ---- W chunk loader: global chunk g -> stage s ----
    auto load_chunk = [&](int g, int s) {
        const __nv_bfloat16* src = Whi + (size_t)(g >> 4) * HIDDEN * HIDDEN
                                       + (g & 15) * 32;
        const uint32_t stb = sb + BST_OFF + s * BSTAGE_B;
#pragma unroll
        for (int it = 0; it < 8; it++) {
            int o = it * 256 + tid;       // 0..2047
            int n = o >> 2, q = o & 3;
            CP_ASYNC16(stb + swzB(n, q), src + (size_t)n * HIDDEN + q * 8);
        }
        CP_COMMIT();
    };

    load_chunk(0, 0);
    load_chunk(1, 1);

    float acc[4][8][4];
#pragma unroll
    for (int i = 0; i < 4; i++)
#pragma unroll
        for (int j = 0; j < 8; j++)
#pragma unroll
            for (int k = 0; k < 4; k++) acc[i][j][k] = 0.f;

    const int a_row = lane & 15;
    const int a_kh  = lane >> 4;
    const int b_rlo = lane & 7;
    const int b_kh  = (lane >> 3) & 1;
    const int b_nn  = lane >> 4;
    const int t4r   = lane >> 2;
    const int t2c   = (lane & 3) * 2;
    const float gain = 1.41421356237309515f;

    for (int g = 0; g < NUM_LAYERS * 16; g++) {
        if (g >= NUM_LAYERS * 16 - 2) asm volatile("cp.async.wait_group 0;" ::: "memory");
        else                          asm volatile("cp.async.wait_group 1;" ::: "memory");
        __syncthreads();
        if (g + 2 < NUM_LAYERS * 16) load_chunk(g + 2, (g + 2) % 3);

        const uint32_t st  = sb + BST_OFF + (g % 3) * BSTAGE_B;
        const int kq0 = (g & 15) * 4;     // chunk's first 16B quad in X row
#pragma unroll
        for (int kh = 0; kh < 2; kh++) {
            uint32_t bf[4][4];
#pragma unroll
            for (int nj = 0; nj < 4; nj++) {
                int rB = wn * 64 + nj * 16 + b_nn * 8 + b_rlo;
                LDSM_X4(bf[nj], st + swzB(rB, kh * 2 + b_kh));
            }
#pragma unroll
            for (int mi = 0; mi < 4; mi++) {
                int rA = mi * 16 + a_row;
                uint32_t af[4];
                LDSM_X4(af, sb + X_OFF + xbyte(rA, (kq0 + kh * 2 + a_kh) * 16));
#pragma unroll
                for (int nj = 0; nj < 4; nj++) {
                    MMA16816(acc[mi][nj * 2 + 0], af, (&bf[nj][0]));
                    MMA16816(acc[mi][nj * 2 + 1], af, (&bf[nj][2]));
                }
            }
        }

        if ((g & 15) == 15) {
            const int l = g >> 4;
            const float* bl = bias + l * HIDDEN;
            __syncthreads();              // all LDSM-from-X of this layer done

            if (l < NUM_LAYERS - 1) {
                // ---- inter-layer epilogue: bias+lrelu -> bf16 -> X in place ----
#pragma unroll
                for (int ni = 0; ni < 8; ni++) {
                    const int c0 = wn * 64 + ni * 8 + t2c;
                    float2 b2 = *(const float2*)(bl + c0);
                    const float bb0 = b2.x * 0.01f, bb1 = b2.y * 0.01f;
#pragma unroll
                    for (int mi = 0; mi < 4; mi++) {
                        const int r = mi * 16 + t4r;
                        float v0 = acc[mi][ni][0] + bb0;
                        float v1 = acc[mi][ni][1] + bb1;
                        float v2 = acc[mi][ni][2] + bb0;
                        float v3 = acc[mi][ni][3] + bb1;
                        v0 = (v0 > 0.f ? v0 : 0.2f * v0) * gain;
                        v1 = (v1 > 0.f ? v1 : 0.2f * v1) * gain;
                        v2 = (v2 > 0.f ? v2 : 0.2f * v2) * gain;
                        v3 = (v3 > 0.f ? v3 : 0.2f * v3) * gain;
                        *(uint32_t*)(smem + X_OFF + xbyte(r,     c0 * 2)) = pk2(v0, v1);
                        *(uint32_t*)(smem + X_OFF + xbyte(r + 8, c0 * 2)) = pk2(v2, v3);
#pragma unroll
                        for (int k = 0; k < 4; k++) acc[mi][ni][k] = 0.f;
                    }
                }
                // next loop iteration's __syncthreads orders X before LDSM
            } else {
                // ---- final epilogue: fp32 stage (64x512 @0, 128KB) + bcast ----
#pragma unroll
                for (int ni = 0; ni < 8; ni++) {
                    const int c0 = wn * 64 + ni * 8 + t2c;
                    float2 b2 = *(const float2*)(bl + c0);
                    const float bb0 = b2.x * 0.01f, bb1 = b2.y * 0.01f;
#pragma unroll
                    for (int mi = 0; mi < 4; mi++) {
                        const int r = mi * 16 + t4r;
                        float v0 = acc[mi][ni][0] + bb0;
                        float v1 = acc[mi][ni][1] + bb1;
                        float v2 = acc[mi][ni][2] + bb0;
                        float v3 = acc[mi][ni][3] + bb1;
                        v0 = (v0 > 0.f ? v0 : 0.2f * v0) * gain;
                        v1 = (v1 > 0.f ? v1 : 0.2f * v1) * gain;
                        v2 = (v2 > 0.f ? v2 : 0.2f * v2) * gain;
                        v3 = (v3 > 0.f ? v3 : 0.2f * v3) * gain;
                        *(float2*)(smem + (size_t)r * 2048 + c0 * 4)       = make_float2(v0, v1);
                        *(float2*)(smem + (size_t)(r + 8) * 2048 + c0 * 4) = make_float2(v2, v3);
                    }
                }
                __syncthreads();
                // stream 64 rows x 16 copies, fully coalesced float4
                for (int it = 0; it < 512; it++) {
                    int idx = it * 256 + tid;        // 0..131071 float4s
                    int f4  = idx & 127;
                    int j   = (idx >> 7) & 15;
                    int row = idx >> 11;             // 0..63
                    float4 v = *(const float4*)(smem + (size_t)row * 2048 + f4 * 16);
                    *(float4*)(outF + ((size_t)(m0 + row) * NUM_OUTPUTS + j) * HIDDEN
                                    + f4 * 4) = v;
                }
            }
        }
    }
}

// ---------------------------------------------------------------------------
extern "C" void kernel_launch(void* const* d_in, const int* in_sizes, int n_in,
                              void* d_out, int out_size) {
    const float* z    = (const float*)d_in[0];
    const float* w    = (const float*)d_in[1];
    const float* bias = (const float*)d_in[2];
    float* out = (float*)d_out;

    __nv_bfloat16 *whi, *ahi;
    cudaGetSymbolAddress((void**)&whi, g_whi);
    cudaGetSymbolAddress((void**)&ahi, g_ahi);

    cudaFuncSetAttribute(fused_mlp_kernel,
                         cudaFuncAttributeMaxDynamicSharedMemorySize, SMEM_BYTES);

    // 1) weight scale -> bf16
    wprep_kernel<<<2048, 256>>>(w, whi);
    // 2) pixel norm -> bf16
    pixnorm_kernel<<<BATCH / 8, dim3(32, 8)>>>(z, ahi);
    // 3) fused 8-layer network + broadcast
    fused_mlp_kernel<<<BATCH / 64, 256, SMEM_BYTES>>>(ahi, whi, bias, out);
}

// round 11
// speedup vs baseline: 2.6039x; 1.0001x over previous
#include <cuda_runtime.h>
#include <cuda_bf16.h>
#include <cstdint>

#define HIDDEN      512
#define NUM_LAYERS  8
#define BATCH       16384
#define NUM_OUTPUTS 16

// ---------------- device scratch (allocation-free rule) ----------------
__device__ __nv_bfloat16 g_whi[NUM_LAYERS * HIDDEN * HIDDEN];  // 4 MB
__device__ __nv_bfloat16 g_ahi[BATCH * HIDDEN];                // 16 MB

// ---------------- helpers ----------------
__device__ __forceinline__ uint32_t smem_u32(const void* p) {
    return (uint32_t)__cvta_generic_to_shared(p);
}

#define CP_ASYNC16(dst, src) \
    asm volatile("cp.async.cg.shared.global [%0], [%1], 16;" :: "r"(dst), "l"(src))
#define CP_COMMIT() asm volatile("cp.async.commit_group;" ::: "memory")

#define LDSM_X4(r, addr)                                                        \
    asm volatile("ldmatrix.sync.aligned.m8n8.x4.shared.b16 {%0,%1,%2,%3}, [%4];"\
        : "=r"((r)[0]), "=r"((r)[1]), "=r"((r)[2]), "=r"((r)[3]) : "r"(addr))

#define MMA16816(d, a, b)                                                       \
    asm volatile("mma.sync.aligned.m16n8k16.row.col.f32.bf16.bf16.f32 "         \
        "{%0,%1,%2,%3},{%4,%5,%6,%7},{%8,%9},{%0,%1,%2,%3};"                    \
        : "+f"((d)[0]), "+f"((d)[1]), "+f"((d)[2]), "+f"((d)[3])                \
        : "r"((a)[0]), "r"((a)[1]), "r"((a)[2]), "r"((a)[3]),                   \
          "r"((b)[0]), "r"((b)[1]))

__device__ __forceinline__ uint32_t pk2(float a, float b) {
    __nv_bfloat162 t = __floats2bfloat162_rn(a, b);
    return *reinterpret_cast<uint32_t*>(&t);
}

// B-stage swizzle: 64B rows of 4x16B quads; q ^= (r>>1)&3
__device__ __forceinline__ uint32_t swzB(int r, int q) {
    return (uint32_t)(r * 64 + ((q ^ ((r >> 1) & 3)) << 4));
}
// X swizzle: 1024B rows; within each 128B block, quad q ^= (r&7)
__device__ __forceinline__ uint32_t xbyte(int r, int cbyte) {
    int blk = cbyte >> 7;
    int q   = (cbyte >> 4) & 7;
    int o   = cbyte & 15;
    return (uint32_t)(r * 1024 + blk * 128 + ((q ^ (r & 7)) << 4) + o);
}

// ---------------- weight prep: W*wscale -> bf16 ----------------
__global__ void wprep_kernel(const float* __restrict__ w,
                             __nv_bfloat16* __restrict__ whi) {
    size_t base = ((size_t)blockIdx.x * 256 + threadIdx.x) * 4;
    const float ws = 4.4194173824159216e-4f;  // 0.01 / sqrt(512)
    float4 v = *(const float4*)(w + base);
    uint2 H;
    H.x = pk2(v.x * ws, v.y * ws);
    H.y = pk2(v.z * ws, v.w * ws);
    *(uint2*)(whi + base) = H;
}

// ---------------- pixel norm -> bf16 ----------------
__global__ void pixnorm_kernel(const float* __restrict__ z,
                               __nv_bfloat16* __restrict__ ohi) {
    int row  = blockIdx.x * 8 + threadIdx.y;
    int lane = threadIdx.x;
    const float4* zr = (const float4*)(z + (size_t)row * HIDDEN);
    float4 v[4];
    float ss = 0.f;
#pragma unroll
    for (int i = 0; i < 4; i++) {
        v[i] = zr[lane + 32 * i];
        ss += v[i].x * v[i].x + v[i].y * v[i].y + v[i].z * v[i].z + v[i].w * v[i].w;
    }
#pragma unroll
    for (int o = 16; o > 0; o >>= 1) ss += __shfl_xor_sync(0xffffffff, ss, o);
    float s = rsqrtf(ss * (1.0f / 512.0f) + 1e-8f);
#pragma unroll
    for (int i = 0; i < 4; i++) {
        float4 t = v[i];
        uint2 H;
        H.x = pk2(t.x * s, t.y * s);
        H.y = pk2(t.z * s, t.w * s);
        *(uint2*)(ohi + (size_t)row * HIDDEN + 4 * (lane + 32 * i)) = H;
    }
}

// ---------------- fused 8-layer mapping network ----------------------------
// One CTA owns 64 batch rows through ALL 8 layers. x resident in smem (bf16,
// rewritten in place per layer). W streams via 3-stage cp.async (32-k chunks,
// 16 chunks/layer, 128 chunks total, continuous across layers).
// 256 threads = 8 warps, warp tile 64(M) x 64(N) (wn = warp, all warps share A).
// SMEM: X[64x1024B]=64K @0 | Bstage 3x32K @65536. Final fp32 staging reuses @0.
#define X_OFF    0
#define BST_OFF  65536
#define BSTAGE_B 32768
#define SMEM_BYTES (BST_OFF + 3 * BSTAGE_B)   // 163840

__global__ __launch_bounds__(256, 1) void fused_mlp_kernel(
    const __nv_bfloat16* __restrict__ Ahi,
    const __nv_bfloat16* __restrict__ Whi,
    const float* __restrict__ bias,
    float* __restrict__ outF)
{
    extern __shared__ char smem[];
    const uint32_t sb = smem_u32(smem);
    const int tid  = threadIdx.x;
    const int lane = tid & 31;
    const int wn   = tid >> 5;            // 0..7: 64-col slice
    const int m0   = blockIdx.x * 64;

    // ---- initial X load: 64 rows x 1024B, swizzled ----
#pragma unroll
    for (int it = 0; it < 16; it++) {
        int o = it * 256 + tid;           // 0..4095 (16B quads)
        int r = o >> 6, kq = o & 63;
        CP_ASYNC16(sb + X_OFF + xbyte(r, kq * 16),
                   Ahi + (size_t)(m0 + r) * HIDDEN + kq * 8);
    }
    CP_COMMIT();

    // ---- W chunk loader: global chunk g -> stage s ----
    auto load_chunk = [&](int g, int s) {
        const __nv_bfloat16* src = Whi + (size_t)(g >> 4) * HIDDEN * HIDDEN
                                       + (g & 15) * 32;
        const uint32_t stb = sb + BST_OFF + s * BSTAGE_B;
#pragma unroll
        for (int it = 0; it < 8; it++) {
            int o = it * 256 + tid;       // 0..2047
            int n = o >> 2, q = o & 3;
            CP_ASYNC16(stb + swzB(n, q), src + (size_t)n * HIDDEN + q * 8);
        }
        CP_COMMIT();
    };

    load_chunk(0, 0);
    load_chunk(1, 1);

    float acc[4][8][4];
#pragma unroll
    for (int i = 0; i < 4; i++)
#pragma unroll
        for (int j = 0; j < 8; j++)
#pragma unroll
            for (int k = 0; k < 4; k++) acc[i][j][k] = 0.f;

    const int a_row = lane & 15;
    const int a_kh  = lane >> 4;
    const int b_rlo = lane & 7;
    const int b_kh  = (lane >> 3) & 1;
    const int b_nn  = lane >> 4;
    const int t4r   = lane >> 2;
    const int t2c   = (lane & 3) * 2;
    const float gain = 1.41421356237309515f;

    for (int g = 0; g < NUM_LAYERS * 16; g++) {
        if (g >= NUM_LAYERS * 16 - 2) asm volatile("cp.async.wait_group 0;" ::: "memory");
        else                          asm volatile("cp.async.wait_group 1;" ::: "memory");
        __syncthreads();
        if (g + 2 < NUM_LAYERS * 16) load_chunk(g + 2, (g + 2) % 3);

        const uint32_t st  = sb + BST_OFF + (g % 3) * BSTAGE_B;
        const int kq0 = (g & 15) * 4;     // chunk's first 16B quad in X row
#pragma unroll
        for (int kh = 0; kh < 2; kh++) {
            uint32_t bf[4][4];
#pragma unroll
            for (int nj = 0; nj < 4; nj++) {
                int rB = wn * 64 + nj * 16 + b_nn * 8 + b_rlo;
                LDSM_X4(bf[nj], st + swzB(rB, kh * 2 + b_kh));
            }
#pragma unroll
            for (int mi = 0; mi < 4; mi++) {
                int rA = mi * 16 + a_row;
                uint32_t af[4];
                LDSM_X4(af, sb + X_OFF + xbyte(rA, (kq0 + kh * 2 + a_kh) * 16));
#pragma unroll
                for (int nj = 0; nj < 4; nj++) {
                    MMA16816(acc[mi][nj * 2 + 0], af, (&bf[nj][0]));
                    MMA16816(acc[mi][nj * 2 + 1], af, (&bf[nj][2]));
                }
            }
        }

        if ((g & 15) == 15) {
            const int l = g >> 4;
            const float* bl = bias + l * HIDDEN;
            __syncthreads();              // all LDSM-from-X of this layer done

            if (l < NUM_LAYERS - 1) {
                // ---- inter-layer epilogue: bias+lrelu -> bf16 -> X in place ----
#pragma unroll
                for (int ni = 0; ni < 8; ni++) {
                    const int c0 = wn * 64 + ni * 8 + t2c;
                    float2 b2 = *(const float2*)(bl + c0);
                    const float bb0 = b2.x * 0.01f, bb1 = b2.y * 0.01f;
#pragma unroll
                    for (int mi = 0; mi < 4; mi++) {
                        const int r = mi * 16 + t4r;
                        float v0 = acc[mi][ni][0] + bb0;
                        float v1 = acc[mi][ni][1] + bb1;
                        float v2 = acc[mi][ni][2] + bb0;
                        float v3 = acc[mi][ni][3] + bb1;
                        v0 = (v0 > 0.f ? v0 : 0.2f * v0) * gain;
                        v1 = (v1 > 0.f ? v1 : 0.2f * v1) * gain;
                        v2 = (v2 > 0.f ? v2 : 0.2f * v2) * gain;
                        v3 = (v3 > 0.f ? v3 : 0.2f * v3) * gain;
                        *(uint32_t*)(smem + X_OFF + xbyte(r,     c0 * 2)) = pk2(v0, v1);
                        *(uint32_t*)(smem + X_OFF + xbyte(r + 8, c0 * 2)) = pk2(v2, v3);
#pragma unroll
                        for (int k = 0; k < 4; k++) acc[mi][ni][k] = 0.f;
                    }
                }
                // next loop iteration's __syncthreads orders X before LDSM
            } else {
                // ---- final epilogue: fp32 stage (64x512 @0, 128KB) + bcast ----
#pragma unroll
                for (int ni = 0; ni < 8; ni++) {
                    const int c0 = wn * 64 + ni * 8 + t2c;
                    float2 b2 = *(const float2*)(bl + c0);
                    const float bb0 = b2.x * 0.01f, bb1 = b2.y * 0.01f;
#pragma unroll
                    for (int mi = 0; mi < 4; mi++) {
                        const int r = mi * 16 + t4r;
                        float v0 = acc[mi][ni][0] + bb0;
                        float v1 = acc[mi][ni][1] + bb1;
                        float v2 = acc[mi][ni][2] + bb0;
                        float v3 = acc[mi][ni][3] + bb1;
                        v0 = (v0 > 0.f ? v0 : 0.2f * v0) * gain;
                        v1 = (v1 > 0.f ? v1 : 0.2f * v1) * gain;
                        v2 = (v2 > 0.f ? v2 : 0.2f * v2) * gain;
                        v3 = (v3 > 0.f ? v3 : 0.2f * v3) * gain;
                        *(float2*)(smem + (size_t)r * 2048 + c0 * 4)       = make_float2(v0, v1);
                        *(float2*)(smem + (size_t)(r + 8) * 2048 + c0 * 4) = make_float2(v2, v3);
                    }
                }
                __syncthreads();
                // stream 64 rows x 16 copies, fully coalesced float4
                for (int it = 0; it < 512; it++) {
                    int idx = it * 256 + tid;        // 0..131071 float4s
                    int f4  = idx & 127;
                    int j   = (idx >> 7) & 15;
                    int row = idx >> 11;             // 0..63
                    float4 v = *(const float4*)(smem + (size_t)row * 2048 + f4 * 16);
                    *(float4*)(outF + ((size_t)(m0 + row) * NUM_OUTPUTS + j) * HIDDEN
                                    + f4 * 4) = v;
                }
            }
        }
    }
}

// ---------------------------------------------------------------------------
extern "C" void kernel_launch(void* const* d_in, const int* in_sizes, int n_in,
                              void* d_out, int out_size) {
    const float* z    = (const float*)d_in[0];
    const float* w    = (const float*)d_in[1];
    const float* bias = (const float*)d_in[2];
    float* out = (float*)d_out;

    __nv_bfloat16 *whi, *ahi;
    cudaGetSymbolAddress((void**)&whi, g_whi);
    cudaGetSymbolAddress((void**)&ahi, g_ahi);

    cudaFuncSetAttribute(fused_mlp_kernel,
                         cudaFuncAttributeMaxDynamicSharedMemorySize, SMEM_BYTES);

    // 1) weight scale -> bf16
    wprep_kernel<<<2048, 256>>>(w, whi);
    // 2) pixel norm -> bf16
    pixnorm_kernel<<<BATCH / 8, dim3(32, 8)>>>(z, ahi);
    // 3) fused 8-layer network + broadcast
    fused_mlp_kernel<<<BATCH / 64, 256, SMEM_BYTES>>>(ahi, whi, bias, out);
}